// round 14
// baseline (speedup 1.0000x reference)
#include <cuda_runtime.h>
#include <cuda_fp16.h>
#include <math.h>
#include <stdint.h>

// ---------------------------------------------------------------------------
// ResidualDenoiser via HMMA (mma.sync fp16, fp32 acc), pure fp16 inference.
// Layers 0-2: CTA tile 128x256, 512 threads, warp tile 32x64, 16 warps/SM.
// Layer 3:    CTA tile 128x128, 256 threads (N=256 -> grid 128 CTAs).
//
// Activation buffer (width 3328, fp16): [ h2 (1024) | h1 (1024) | h0 (1024) | x (256) ]
// ---------------------------------------------------------------------------

#define B_ROWS 8192
#define ACT_W  3328
#define NSEG   10
#define EPS    1e-5f

#define KC  32
#define NSTAGE 4
#define ROWB 80                  // padded row stride (bytes) for 64B of k data
#define ATILEB (128 * ROWB)      // A tile bytes (128 rows)

// wide kernel (layers 0-2)
#define W_TBN 256
#define W_STAGEB ((128 + W_TBN) * ROWB)          // 30720
#define SMEM_WIDE (NSTAGE * W_STAGEB)            // 122880

// narrow kernel (layer 3)
#define N_TBN 128
#define N_STAGEB ((128 + N_TBN) * ROWB)          // 20480
#define SMEM_NARROW (NSTAGE * N_STAGEB)          // 81920

// weight concat offsets (elements)
#define WOFF0 0
#define WOFF1 262144
#define WOFF2 1572864
#define WOFF3 3932160
#define WTOT  4784128

__device__ __half g_act[(size_t)B_ROWS * ACT_W];
__device__ __half g_w[WTOT];
__device__ float  g_logits[(size_t)B_ROWS * 256];

__device__ __forceinline__ uint32_t smem_u32(const void* p) {
    uint32_t a;
    asm("{ .reg .u64 t; cvta.to.shared.u64 t, %1; cvt.u32.u64 %0, t; }" : "=r"(a) : "l"(p));
    return a;
}

#define CP_ASYNC16(dst, src) \
    asm volatile("cp.async.cg.shared.global [%0], [%1], 16;" :: "r"(dst), "l"(src))
#define CP_COMMIT()  asm volatile("cp.async.commit_group;" ::: "memory")
#define CP_WAIT3()   asm volatile("cp.async.wait_group 3;" ::: "memory")
#define CP_WAIT0()   asm volatile("cp.async.wait_group 0;" ::: "memory")

#define LDSM_X4(r0, r1, r2, r3, a) \
    asm volatile("ldmatrix.sync.aligned.m8n8.x4.shared.b16 {%0,%1,%2,%3}, [%4];" \
        : "=r"(r0), "=r"(r1), "=r"(r2), "=r"(r3) : "r"(a))

#define MMA_F16(d, a, b) \
    asm volatile("mma.sync.aligned.m16n8k16.row.col.f32.f16.f16.f32 " \
        "{%0,%1,%2,%3}, {%4,%5,%6,%7}, {%8,%9}, {%0,%1,%2,%3};" \
        : "+f"((d)[0]), "+f"((d)[1]), "+f"((d)[2]), "+f"((d)[3]) \
        : "r"((a)[0]), "r"((a)[1]), "r"((a)[2]), "r"((a)[3]), \
          "r"((b)[0]), "r"((b)[1]))

// ---------------------------------------------------------------------------
// WIDE kernel: C[r,f] = sum_k A[r,k]*W[f,k], CTA 128x256, 512 threads.
// Warp grid 4(M) x 4(N); warp tile 32x64. Fused bias+BN+ReLU -> fp16 out.
// ---------------------------------------------------------------------------
__global__ __launch_bounds__(512, 1)
void mma_gemm_wide(const __half* __restrict__ A,
                   const __half* __restrict__ Wh,
                   const float* __restrict__ bias,
                   const float* __restrict__ gg, const float* __restrict__ be,
                   const float* __restrict__ rm, const float* __restrict__ rv,
                   __half* __restrict__ Ch, int K)
{
    extern __shared__ char smem[];
    const uint32_t sbuf = smem_u32(smem);

    const int tid    = threadIdx.x;
    const int lane   = tid & 31;
    const int wid    = tid >> 5;       // 0..15
    const int warp_m = wid & 3;        // 4 warps over M (32 rows each)
    const int warp_n = wid >> 2;       // 4 warps over N (64 cols each)
    const int row0   = blockIdx.y * 128;
    const int col0   = blockIdx.x * W_TBN;

    const int n_iter = K / KC;

    float acc[2][8][4];
    #pragma unroll
    for (int i = 0; i < 2; i++)
        #pragma unroll
        for (int j = 0; j < 8; j++)
            #pragma unroll
            for (int l = 0; l < 4; l++)
                acc[i][j][l] = 0.f;

    // stage loader: (128 + 256) rows * 4 chunks of 16B = 1536 = 3 x 512
    auto load_stage = [&](int s) {
        const int k0  = s * KC;
        const uint32_t sb = sbuf + (s % NSTAGE) * W_STAGEB;
        #pragma unroll
        for (int i = 0; i < 3; i++) {
            const int idx = tid + (i << 9);
            const int c   = idx & 3;
            if (idx < 512) {
                const int r = idx >> 2;
                CP_ASYNC16(sb + r * ROWB + c * 16,
                           A + (size_t)(row0 + r) * ACT_W + k0 + c * 8);
            } else {
                const int r = (idx - 512) >> 2;   // 0..255
                CP_ASYNC16(sb + ATILEB + r * ROWB + c * 16,
                           Wh + (size_t)(col0 + r) * K + k0 + c * 8);
            }
        }
    };

    const uint32_t a_off = (uint32_t)((warp_m * 32 + (lane & 15)) * ROWB + (lane >> 4) * 16);
    const uint32_t b_off = (uint32_t)((warp_n * 64 + (lane >> 4) * 8 + (lane & 7)) * ROWB
                                      + ((lane >> 3) & 1) * 16);

    load_stage(0); CP_COMMIT();
    load_stage(1); CP_COMMIT();
    load_stage(2); CP_COMMIT();

    for (int it = 0; it < n_iter; it++) {
        if (it + 3 < n_iter) load_stage(it + 3);
        CP_COMMIT();
        CP_WAIT3();
        __syncthreads();

        const uint32_t sb = sbuf + (it % NSTAGE) * W_STAGEB;
        #pragma unroll
        for (int kk = 0; kk < 2; kk++) {          // two k16 steps
            uint32_t ah[2][4], bh[8][2];
            #pragma unroll
            for (int mt = 0; mt < 2; mt++) {
                const uint32_t aa = sb + a_off + mt * (16 * ROWB) + kk * 32;
                LDSM_X4(ah[mt][0], ah[mt][1], ah[mt][2], ah[mt][3], aa);
            }
            #pragma unroll
            for (int bt = 0; bt < 4; bt++) {
                const uint32_t ba = sb + ATILEB + b_off + bt * (16 * ROWB) + kk * 32;
                uint32_t r0, r1, r2, r3;
                LDSM_X4(r0, r1, r2, r3, ba);
                bh[bt * 2][0] = r0;     bh[bt * 2][1] = r1;
                bh[bt * 2 + 1][0] = r2; bh[bt * 2 + 1][1] = r3;
            }
            #pragma unroll
            for (int mt = 0; mt < 2; mt++)
                #pragma unroll
                for (int nt = 0; nt < 8; nt++)
                    MMA_F16(acc[mt][nt], ah[mt], bh[nt]);
        }
        __syncthreads();
    }
    CP_WAIT0();

    // epilogue: bias + BN + ReLU -> fp16
    #pragma unroll
    for (int nt = 0; nt < 8; nt++) {
        const int f = col0 + warp_n * 64 + nt * 8 + (lane & 3) * 2;
        const float bs0 = bias[f], bs1 = bias[f + 1];
        const float sc0 = gg[f]     * rsqrtf(rv[f]     + EPS);
        const float sc1 = gg[f + 1] * rsqrtf(rv[f + 1] + EPS);
        const float sh0 = be[f]     - rm[f]     * sc0;
        const float sh1 = be[f + 1] - rm[f + 1] * sc1;
        #pragma unroll
        for (int mt = 0; mt < 2; mt++) {
            const int r = row0 + warp_m * 32 + mt * 16 + (lane >> 2);
            #pragma unroll
            for (int half = 0; half < 2; half++) {
                const int rr = r + half * 8;
                float v0 = acc[mt][nt][half * 2]     + bs0;
                float v1 = acc[mt][nt][half * 2 + 1] + bs1;
                v0 = fmaxf(fmaf(v0, sc0, sh0), 0.f);
                v1 = fmaxf(fmaf(v1, sc1, sh1), 0.f);
                __half2 hp; hp.x = __float2half(v0); hp.y = __float2half(v1);
                *reinterpret_cast<__half2*>(Ch + (size_t)rr * ACT_W + f) = hp;
            }
        }
    }
}

// ---------------------------------------------------------------------------
// NARROW kernel (layer 3): CTA 128x128, 256 threads, warp tile 64x32.
// bias only -> fp32 logits (row stride 256).
// ---------------------------------------------------------------------------
__global__ __launch_bounds__(256)
void mma_gemm_l3(const __half* __restrict__ A,
                 const __half* __restrict__ Wh,
                 const float* __restrict__ bias,
                 float* __restrict__ Cf, int K)
{
    extern __shared__ char smem[];
    const uint32_t sbuf = smem_u32(smem);

    const int tid    = threadIdx.x;
    const int lane   = tid & 31;
    const int wid    = tid >> 5;
    const int warp_m = wid & 1;
    const int warp_n = wid >> 1;
    const int row0   = blockIdx.y * 128;
    const int col0   = blockIdx.x * N_TBN;

    const int n_iter = K / KC;

    float acc[4][4][4];
    #pragma unroll
    for (int i = 0; i < 4; i++)
        #pragma unroll
        for (int j = 0; j < 4; j++)
            #pragma unroll
            for (int l = 0; l < 4; l++)
                acc[i][j][l] = 0.f;

    auto load_stage = [&](int s) {
        const int k0  = s * KC;
        const uint32_t sb = sbuf + (s % NSTAGE) * N_STAGEB;
        #pragma unroll
        for (int i = 0; i < 4; i++) {
            const int idx = tid + (i << 8);
            const int c   = idx & 3;
            if (idx < 512) {
                const int r = idx >> 2;
                CP_ASYNC16(sb + r * ROWB + c * 16,
                           A + (size_t)(row0 + r) * ACT_W + k0 + c * 8);
            } else {
                const int r = (idx - 512) >> 2;
                CP_ASYNC16(sb + ATILEB + r * ROWB + c * 16,
                           Wh + (size_t)(col0 + r) * K + k0 + c * 8);
            }
        }
    };

    const uint32_t a_off = (uint32_t)((warp_m * 64 + (lane & 15)) * ROWB + (lane >> 4) * 16);
    const uint32_t b_off = (uint32_t)((warp_n * 32 + (lane >> 4) * 8 + (lane & 7)) * ROWB
                                      + ((lane >> 3) & 1) * 16);

    load_stage(0); CP_COMMIT();
    load_stage(1); CP_COMMIT();
    load_stage(2); CP_COMMIT();

    for (int it = 0; it < n_iter; it++) {
        if (it + 3 < n_iter) load_stage(it + 3);
        CP_COMMIT();
        CP_WAIT3();
        __syncthreads();

        const uint32_t sb = sbuf + (it % NSTAGE) * N_STAGEB;
        #pragma unroll
        for (int kk = 0; kk < 2; kk++) {
            uint32_t ah[4][4], bh[4][2];
            #pragma unroll
            for (int mt = 0; mt < 4; mt++) {
                const uint32_t aa = sb + a_off + mt * (16 * ROWB) + kk * 32;
                LDSM_X4(ah[mt][0], ah[mt][1], ah[mt][2], ah[mt][3], aa);
            }
            #pragma unroll
            for (int bt = 0; bt < 2; bt++) {
                const uint32_t ba = sb + ATILEB + b_off + bt * (16 * ROWB) + kk * 32;
                uint32_t r0, r1, r2, r3;
                LDSM_X4(r0, r1, r2, r3, ba);
                bh[bt * 2][0] = r0;     bh[bt * 2][1] = r1;
                bh[bt * 2 + 1][0] = r2; bh[bt * 2 + 1][1] = r3;
            }
            #pragma unroll
            for (int mt = 0; mt < 4; mt++)
                #pragma unroll
                for (int nt = 0; nt < 4; nt++)
                    MMA_F16(acc[mt][nt], ah[mt], bh[nt]);
        }
        __syncthreads();
    }
    CP_WAIT0();

    #pragma unroll
    for (int nt = 0; nt < 4; nt++) {
        const int f = col0 + warp_n * 32 + nt * 8 + (lane & 3) * 2;
        const float bs0 = bias[f], bs1 = bias[f + 1];
        #pragma unroll
        for (int mt = 0; mt < 4; mt++) {
            const int r = row0 + warp_m * 64 + mt * 16 + (lane >> 2);
            #pragma unroll
            for (int half = 0; half < 2; half++) {
                const int rr = r + half * 8;
                float2 o;
                o.x = acc[mt][nt][half * 2]     + bs0;
                o.y = acc[mt][nt][half * 2 + 1] + bs1;
                *reinterpret_cast<float2*>(Cf + (size_t)rr * 256 + f) = o;
            }
        }
    }
}

// ---------------------------------------------------------------------------
// conversions (vectorized: 8 elems / thread)
// ---------------------------------------------------------------------------
__global__ void cvt_w_one(const float* __restrict__ src,
                          __half* __restrict__ dst, int n)
{
    int i = (blockIdx.x * blockDim.x + threadIdx.x) * 8;
    if (i < n) {
        float4 a = *reinterpret_cast<const float4*>(src + i);
        float4 b = *reinterpret_cast<const float4*>(src + i + 4);
        __half2 h[4];
        h[0] = __floats2half2_rn(a.x, a.y);
        h[1] = __floats2half2_rn(a.z, a.w);
        h[2] = __floats2half2_rn(b.x, b.y);
        h[3] = __floats2half2_rn(b.z, b.w);
        *reinterpret_cast<uint4*>(dst + i) = *reinterpret_cast<uint4*>(h);
    }
}

__global__ void cvt_x_kernel(const float* __restrict__ x)
{
    int i = (blockIdx.x * blockDim.x + threadIdx.x) * 8;      // over 8192*256
    int r = i >> 8;
    int c = i & 255;
    float4 a = *reinterpret_cast<const float4*>(x + i);
    float4 b = *reinterpret_cast<const float4*>(x + i + 4);
    __half2 h[4];
    h[0] = __floats2half2_rn(a.x, a.y);
    h[1] = __floats2half2_rn(a.z, a.w);
    h[2] = __floats2half2_rn(b.x, b.y);
    h[3] = __floats2half2_rn(b.z, b.w);
    *reinterpret_cast<uint4*>(g_act + (size_t)r * ACT_W + 3072 + c) =
        *reinterpret_cast<uint4*>(h);
}

// ---------------------------------------------------------------------------
// Segmented softmax (one block per row)
// ---------------------------------------------------------------------------
__global__ void seg_softmax_kernel(const int* __restrict__ seg_ids,
                                   float* __restrict__ out)
{
    __shared__ float vals[256];
    __shared__ int   sseg[256];
    __shared__ float smax[NSEG];
    __shared__ float ssum[NSEG];

    const int row = blockIdx.x;
    const int t   = threadIdx.x;

    float v = g_logits[(size_t)row * 256 + t];
    vals[t] = v;
    sseg[t] = seg_ids[t];
    __syncthreads();

    if (t < NSEG) {
        float m = -3.402823466e+38f;
        for (int i = 0; i < 256; i++)
            if (sseg[i] == t) m = fmaxf(m, vals[i]);
        smax[t] = m;
    }
    __syncthreads();

    const int s = sseg[t];
    float e = expf(v - smax[s]);
    vals[t] = e;
    __syncthreads();

    if (t < NSEG) {
        float sum = 0.f;
        for (int i = 0; i < 256; i++)
            if (sseg[i] == t) sum += vals[i];
        ssum[t] = sum;
    }
    __syncthreads();

    out[(size_t)row * 256 + t] = e / ssum[s];
}

// ---------------------------------------------------------------------------
// Launch
// ---------------------------------------------------------------------------
extern "C" void kernel_launch(void* const* d_in, const int* in_sizes, int n_in,
                              void* d_out, int out_size)
{
    const float* x   = (const float*)d_in[0];
    const float* W0  = (const float*)d_in[1];
    const float* b0  = (const float*)d_in[2];
    const float* g0  = (const float*)d_in[3];
    const float* be0 = (const float*)d_in[4];
    const float* rm0 = (const float*)d_in[5];
    const float* rv0 = (const float*)d_in[6];
    const float* W1  = (const float*)d_in[7];
    const float* b1  = (const float*)d_in[8];
    const float* g1  = (const float*)d_in[9];
    const float* be1 = (const float*)d_in[10];
    const float* rm1 = (const float*)d_in[11];
    const float* rv1 = (const float*)d_in[12];
    const float* W2  = (const float*)d_in[13];
    const float* b2  = (const float*)d_in[14];
    const float* g2  = (const float*)d_in[15];
    const float* be2 = (const float*)d_in[16];
    const float* rm2 = (const float*)d_in[17];
    const float* rv2 = (const float*)d_in[18];
    const float* W3  = (const float*)d_in[19];
    const float* b3  = (const float*)d_in[20];
    const int*   seg = (const int*)d_in[21];

    __half *act = nullptr, *wh = nullptr;
    float* logits = nullptr;
    cudaGetSymbolAddress((void**)&act, g_act);
    cudaGetSymbolAddress((void**)&wh, g_w);
    cudaGetSymbolAddress((void**)&logits, g_logits);

    cudaFuncSetAttribute(mma_gemm_wide, cudaFuncAttributeMaxDynamicSharedMemorySize, SMEM_WIDE);
    cudaFuncSetAttribute(mma_gemm_l3,   cudaFuncAttributeMaxDynamicSharedMemorySize, SMEM_NARROW);

    // prologue: conversions (all sizes divisible by 8*256)
    cvt_x_kernel<<<(B_ROWS * 256) / (256 * 8), 256>>>(x);
    cvt_w_one<<<(1024 * 256) / (256 * 8), 256>>>(W0, wh + WOFF0, 1024 * 256);
    cvt_w_one<<<(1024 * 1280) / (256 * 8), 256>>>(W1, wh + WOFF1, 1024 * 1280);
    cvt_w_one<<<(1024 * 2304) / (256 * 8), 256>>>(W2, wh + WOFF2, 1024 * 2304);
    cvt_w_one<<<(256 * 3328) / (256 * 8), 256>>>(W3, wh + WOFF3, 256 * 3328);

    dim3 gridW(1024 / W_TBN, B_ROWS / 128);    // (4, 64)
    dim3 gridL3(256 / N_TBN, B_ROWS / 128);    // (2, 64)

    mma_gemm_wide<<<gridW, 512, SMEM_WIDE>>>(act + 3072, wh + WOFF0,
                                             b0, g0, be0, rm0, rv0,
                                             act + 2048, 256);
    mma_gemm_wide<<<gridW, 512, SMEM_WIDE>>>(act + 2048, wh + WOFF1,
                                             b1, g1, be1, rm1, rv1,
                                             act + 1024, 1280);
    mma_gemm_wide<<<gridW, 512, SMEM_WIDE>>>(act + 1024, wh + WOFF2,
                                             b2, g2, be2, rm2, rv2,
                                             act, 2304);
    mma_gemm_l3<<<gridL3, 256, SMEM_NARROW>>>(act, wh + WOFF3, b3, logits, 3328);

    seg_softmax_kernel<<<B_ROWS, 256>>>(seg, (float*)d_out);
}

// round 15
// speedup vs baseline: 1.2547x; 1.2547x over previous
#include <cuda_runtime.h>
#include <cuda_fp16.h>
#include <math.h>
#include <stdint.h>

// ---------------------------------------------------------------------------
// ResidualDenoiser via HMMA (mma.sync fp16, fp32 acc), pure fp16 inference.
// CTA tile 128x128, 256 threads, KC=64, 3-stage cp.async, 2 CTAs/SM.
//
// Activation buffer (width 3328, fp16): [ h2 (1024) | h1 (1024) | h0 (1024) | x (256) ]
// ---------------------------------------------------------------------------

#define B_ROWS 8192
#define ACT_W  3328
#define NSEG   10
#define EPS    1e-5f

#define TBM 128
#define TBN 128
#define KC  64
#define NSTAGE 3
#define ROWB 144                 // padded row stride (bytes) for 128B of k data
#define TILEB (128 * ROWB)       // 18432 bytes per tile
#define STAGEB (2 * TILEB)       // A, W : 36864
#define SMEM_BYTES (NSTAGE * STAGEB)   // 110592

// weight concat offsets (elements)
#define WOFF0 0
#define WOFF1 262144
#define WOFF2 1572864
#define WOFF3 3932160
#define WTOT  4784128

__device__ __half g_act[(size_t)B_ROWS * ACT_W];
__device__ __half g_w[WTOT];
__device__ float  g_logits[(size_t)B_ROWS * 256];

__device__ __forceinline__ uint32_t smem_u32(const void* p) {
    uint32_t a;
    asm("{ .reg .u64 t; cvta.to.shared.u64 t, %1; cvt.u32.u64 %0, t; }" : "=r"(a) : "l"(p));
    return a;
}

#define CP_ASYNC16(dst, src) \
    asm volatile("cp.async.cg.shared.global [%0], [%1], 16;" :: "r"(dst), "l"(src))
#define CP_COMMIT()  asm volatile("cp.async.commit_group;" ::: "memory")
#define CP_WAIT2()   asm volatile("cp.async.wait_group 2;" ::: "memory")
#define CP_WAIT0()   asm volatile("cp.async.wait_group 0;" ::: "memory")

#define LDSM_X4(r0, r1, r2, r3, a) \
    asm volatile("ldmatrix.sync.aligned.m8n8.x4.shared.b16 {%0,%1,%2,%3}, [%4];" \
        : "=r"(r0), "=r"(r1), "=r"(r2), "=r"(r3) : "r"(a))

#define MMA_F16(d, a, b) \
    asm volatile("mma.sync.aligned.m16n8k16.row.col.f32.f16.f16.f32 " \
        "{%0,%1,%2,%3}, {%4,%5,%6,%7}, {%8,%9}, {%0,%1,%2,%3};" \
        : "+f"((d)[0]), "+f"((d)[1]), "+f"((d)[2]), "+f"((d)[3]) \
        : "r"((a)[0]), "r"((a)[1]), "r"((a)[2]), "r"((a)[3]), \
          "r"((b)[0]), "r"((b)[1]))

// ---------------------------------------------------------------------------
// GEMM: C[r,f] = sum_k A[r,k]*W[f,k]
//   A row stride ACT_W; W row stride K. 2 warps over M (64), 4 over N (32).
//   BN=true : bias+BN+ReLU -> fp16 out (row stride ACT_W)
//   BN=false: bias         -> fp32 out (row stride 256)
// ---------------------------------------------------------------------------
template <bool BN>
__global__ __launch_bounds__(256, 2)
void mma_gemm(const __half* __restrict__ A,
              const __half* __restrict__ Wh,
              const float* __restrict__ bias,
              const float* __restrict__ gg, const float* __restrict__ be,
              const float* __restrict__ rm, const float* __restrict__ rv,
              __half* __restrict__ Ch,
              float* __restrict__ Cf, int K)
{
    extern __shared__ char smem[];
    const uint32_t sbuf = smem_u32(smem);

    const int tid    = threadIdx.x;
    const int lane   = tid & 31;
    const int wid    = tid >> 5;
    const int warp_m = wid & 1;        // 2 warps over M (64 rows each)
    const int warp_n = wid >> 1;       // 4 warps over N (32 cols each)
    const int row0   = blockIdx.y * TBM;
    const int col0   = blockIdx.x * TBN;

    const int n_iter = K / KC;

    float acc[4][4][4];
    #pragma unroll
    for (int i = 0; i < 4; i++)
        #pragma unroll
        for (int j = 0; j < 4; j++)
            #pragma unroll
            for (int l = 0; l < 4; l++)
                acc[i][j][l] = 0.f;

    // stage loader: 2 tiles * 128 rows * 8 chunks of 16B = 2048 = 8 x 256
    auto load_stage = [&](int s) {
        const int k0  = s * KC;
        const uint32_t sb = sbuf + (s % NSTAGE) * STAGEB;
        #pragma unroll
        for (int i = 0; i < 8; i++) {
            const int idx = tid + (i << 8);       // 0..2047
            const int t   = idx >> 10;            // tile 0..1
            const int w   = idx & 1023;
            const int r   = w >> 3;               // row 0..127
            const int c   = w & 7;                // 16B chunk 0..7
            const uint32_t dst = sb + t * TILEB + r * ROWB + c * 16;
            const __half* src;
            if (t == 0) src = A  + (size_t)(row0 + r) * ACT_W + k0 + c * 8;
            else        src = Wh + (size_t)(col0 + r) * K     + k0 + c * 8;
            CP_ASYNC16(dst, src);
        }
    };

    // ldmatrix per-lane base offsets
    const uint32_t a_off = (uint32_t)((warp_m * 64 + (lane & 15)) * ROWB + (lane >> 4) * 16);
    const uint32_t b_off = (uint32_t)((warp_n * 32 + (lane >> 4) * 8 + (lane & 7)) * ROWB
                                      + ((lane >> 3) & 1) * 16);

    // prologue: stages 0,1
    load_stage(0); CP_COMMIT();
    load_stage(1); CP_COMMIT();

    for (int it = 0; it < n_iter; it++) {
        if (it + 2 < n_iter) load_stage(it + 2);
        CP_COMMIT();
        CP_WAIT2();
        __syncthreads();

        const uint32_t sb = sbuf + (it % NSTAGE) * STAGEB;
        #pragma unroll
        for (int kk = 0; kk < 4; kk++) {         // four k16 steps
            uint32_t ah[4][4], bh[4][2];
            #pragma unroll
            for (int mt = 0; mt < 4; mt++) {
                const uint32_t aa = sb + a_off + mt * (16 * ROWB) + kk * 32;
                LDSM_X4(ah[mt][0], ah[mt][1], ah[mt][2], ah[mt][3], aa);
            }
            #pragma unroll
            for (int bt = 0; bt < 2; bt++) {
                const uint32_t ba = sb + TILEB + b_off + bt * (16 * ROWB) + kk * 32;
                uint32_t r0, r1, r2, r3;
                LDSM_X4(r0, r1, r2, r3, ba);
                bh[bt * 2][0] = r0;     bh[bt * 2][1] = r1;
                bh[bt * 2 + 1][0] = r2; bh[bt * 2 + 1][1] = r3;
            }
            #pragma unroll
            for (int mt = 0; mt < 4; mt++)
                #pragma unroll
                for (int nt = 0; nt < 4; nt++)
                    MMA_F16(acc[mt][nt], ah[mt], bh[nt]);
        }
        __syncthreads();
    }
    CP_WAIT0();

    // ------------------------------ epilogue ------------------------------
    #pragma unroll
    for (int nt = 0; nt < 4; nt++) {
        const int f = col0 + warp_n * 32 + nt * 8 + (lane & 3) * 2;
        const float bs0 = bias[f], bs1 = bias[f + 1];
        float sc0 = 0.f, sh0 = 0.f, sc1 = 0.f, sh1 = 0.f;
        if (BN) {
            sc0 = gg[f]     * rsqrtf(rv[f]     + EPS);
            sc1 = gg[f + 1] * rsqrtf(rv[f + 1] + EPS);
            sh0 = be[f]     - rm[f]     * sc0;
            sh1 = be[f + 1] - rm[f + 1] * sc1;
        }
        #pragma unroll
        for (int mt = 0; mt < 4; mt++) {
            const int r = row0 + warp_m * 64 + mt * 16 + (lane >> 2);
            #pragma unroll
            for (int half = 0; half < 2; half++) {
                const int rr = r + half * 8;
                float v0 = acc[mt][nt][half * 2]     + bs0;
                float v1 = acc[mt][nt][half * 2 + 1] + bs1;
                if (BN) {
                    v0 = fmaxf(fmaf(v0, sc0, sh0), 0.f);
                    v1 = fmaxf(fmaf(v1, sc1, sh1), 0.f);
                    __half2 hp; hp.x = __float2half(v0); hp.y = __float2half(v1);
                    *reinterpret_cast<__half2*>(Ch + (size_t)rr * ACT_W + f) = hp;
                } else {
                    float2 o; o.x = v0; o.y = v1;
                    *reinterpret_cast<float2*>(Cf + (size_t)rr * 256 + f) = o;
                }
            }
        }
    }
}

// ---------------------------------------------------------------------------
// merged weight conversion: one launch for all 4 weight tensors.
// Each 256-thread block covers 2048 consecutive elements of the concatenated
// weight buffer; all region boundaries are multiples of 2048.
// ---------------------------------------------------------------------------
__global__ void cvt_w_all(const float* __restrict__ W0, const float* __restrict__ W1,
                          const float* __restrict__ W2, const float* __restrict__ W3)
{
    const int i = (blockIdx.x * blockDim.x + threadIdx.x) * 8;   // < WTOT
    const float* src;
    int base;
    if (i < WOFF1)      { src = W0; base = WOFF0; }
    else if (i < WOFF2) { src = W1; base = WOFF1; }
    else if (i < WOFF3) { src = W2; base = WOFF2; }
    else                { src = W3; base = WOFF3; }
    const int j = i - base;
    float4 a = *reinterpret_cast<const float4*>(src + j);
    float4 b = *reinterpret_cast<const float4*>(src + j + 4);
    __half2 h[4];
    h[0] = __floats2half2_rn(a.x, a.y);
    h[1] = __floats2half2_rn(a.z, a.w);
    h[2] = __floats2half2_rn(b.x, b.y);
    h[3] = __floats2half2_rn(b.z, b.w);
    *reinterpret_cast<uint4*>(g_w + i) = *reinterpret_cast<uint4*>(h);
}

__global__ void cvt_x_kernel(const float* __restrict__ x)
{
    int i = (blockIdx.x * blockDim.x + threadIdx.x) * 8;      // over 8192*256
    int r = i >> 8;
    int c = i & 255;
    float4 a = *reinterpret_cast<const float4*>(x + i);
    float4 b = *reinterpret_cast<const float4*>(x + i + 4);
    __half2 h[4];
    h[0] = __floats2half2_rn(a.x, a.y);
    h[1] = __floats2half2_rn(a.z, a.w);
    h[2] = __floats2half2_rn(b.x, b.y);
    h[3] = __floats2half2_rn(b.z, b.w);
    *reinterpret_cast<uint4*>(g_act + (size_t)r * ACT_W + 3072 + c) =
        *reinterpret_cast<uint4*>(h);
}

// ---------------------------------------------------------------------------
// Segmented softmax (one block per row)
// ---------------------------------------------------------------------------
__global__ void seg_softmax_kernel(const int* __restrict__ seg_ids,
                                   float* __restrict__ out)
{
    __shared__ float vals[256];
    __shared__ int   sseg[256];
    __shared__ float smax[NSEG];
    __shared__ float ssum[NSEG];

    const int row = blockIdx.x;
    const int t   = threadIdx.x;

    float v = g_logits[(size_t)row * 256 + t];
    vals[t] = v;
    sseg[t] = seg_ids[t];
    __syncthreads();

    if (t < NSEG) {
        float m = -3.402823466e+38f;
        for (int i = 0; i < 256; i++)
            if (sseg[i] == t) m = fmaxf(m, vals[i]);
        smax[t] = m;
    }
    __syncthreads();

    const int s = sseg[t];
    float e = expf(v - smax[s]);
    vals[t] = e;
    __syncthreads();

    if (t < NSEG) {
        float sum = 0.f;
        for (int i = 0; i < 256; i++)
            if (sseg[i] == t) sum += vals[i];
        ssum[t] = sum;
    }
    __syncthreads();

    out[(size_t)row * 256 + t] = e / ssum[s];
}

// ---------------------------------------------------------------------------
// Launch
// ---------------------------------------------------------------------------
extern "C" void kernel_launch(void* const* d_in, const int* in_sizes, int n_in,
                              void* d_out, int out_size)
{
    const float* x   = (const float*)d_in[0];
    const float* W0  = (const float*)d_in[1];
    const float* b0  = (const float*)d_in[2];
    const float* g0  = (const float*)d_in[3];
    const float* be0 = (const float*)d_in[4];
    const float* rm0 = (const float*)d_in[5];
    const float* rv0 = (const float*)d_in[6];
    const float* W1  = (const float*)d_in[7];
    const float* b1  = (const float*)d_in[8];
    const float* g1  = (const float*)d_in[9];
    const float* be1 = (const float*)d_in[10];
    const float* rm1 = (const float*)d_in[11];
    const float* rv1 = (const float*)d_in[12];
    const float* W2  = (const float*)d_in[13];
    const float* b2  = (const float*)d_in[14];
    const float* g2  = (const float*)d_in[15];
    const float* be2 = (const float*)d_in[16];
    const float* rm2 = (const float*)d_in[17];
    const float* rv2 = (const float*)d_in[18];
    const float* W3  = (const float*)d_in[19];
    const float* b3  = (const float*)d_in[20];
    const int*   seg = (const int*)d_in[21];

    __half *act = nullptr, *wh = nullptr;
    float* logits = nullptr;
    cudaGetSymbolAddress((void**)&act, g_act);
    cudaGetSymbolAddress((void**)&wh, g_w);
    cudaGetSymbolAddress((void**)&logits, g_logits);

    cudaFuncSetAttribute(mma_gemm<true>,  cudaFuncAttributeMaxDynamicSharedMemorySize, SMEM_BYTES);
    cudaFuncSetAttribute(mma_gemm<false>, cudaFuncAttributeMaxDynamicSharedMemorySize, SMEM_BYTES);

    // prologue: conversions
    cvt_x_kernel<<<(B_ROWS * 256) / (256 * 8), 256>>>(x);
    cvt_w_all<<<WTOT / (256 * 8), 256>>>(W0, W1, W2, W3);

    dim3 blk(256);
    dim3 grid1024(1024 / TBN, B_ROWS / TBM);   // (8, 64)
    dim3 grid256(256 / TBN, B_ROWS / TBM);     // (2, 64)

    mma_gemm<true><<<grid1024, blk, SMEM_BYTES>>>(act + 3072, wh + WOFF0,
                                                  b0, g0, be0, rm0, rv0,
                                                  act + 2048, nullptr, 256);
    mma_gemm<true><<<grid1024, blk, SMEM_BYTES>>>(act + 2048, wh + WOFF1,
                                                  b1, g1, be1, rm1, rv1,
                                                  act + 1024, nullptr, 1280);
    mma_gemm<true><<<grid1024, blk, SMEM_BYTES>>>(act + 1024, wh + WOFF2,
                                                  b2, g2, be2, rm2, rv2,
                                                  act, nullptr, 2304);
    mma_gemm<false><<<grid256, blk, SMEM_BYTES>>>(act, wh + WOFF3,
                                                  b3, nullptr, nullptr, nullptr, nullptr,
                                                  nullptr, logits, 3328);

    seg_softmax_kernel<<<B_ROWS, 256>>>(seg, (float*)d_out);
}

// round 16
// speedup vs baseline: 1.2794x; 1.0197x over previous
#include <cuda_runtime.h>
#include <cuda_fp16.h>
#include <math.h>
#include <stdint.h>

// ---------------------------------------------------------------------------
// ResidualDenoiser via HMMA (mma.sync fp16, fp32 acc), pure fp16 inference.
// Layers 0-2: CTA 128x128, 256 thr, KC=64, 3-stage cp.async, 2 CTAs/SM.
// Layer 3:    CTA 128x64 (N=256 -> 256 CTAs, full occupancy).
//
// Activation buffer (width 3328, fp16): [ h2 (1024) | h1 (1024) | h0 (1024) | x (256) ]
// ---------------------------------------------------------------------------

#define B_ROWS 8192
#define ACT_W  3328
#define NSEG   10
#define EPS    1e-5f

#define TBM 128
#define TBN 128
#define KC  64
#define NSTAGE 3
#define ROWB 144                 // padded row stride (bytes) for 128B of k data
#define TILEB (128 * ROWB)       // 18432 bytes per A tile
#define STAGEB (2 * TILEB)       // A, W : 36864
#define SMEM_BYTES (NSTAGE * STAGEB)   // 110592

// layer-3 kernel: CTA 128x64
#define L3_TBN 64
#define L3_WTILEB (L3_TBN * ROWB)            // 9216
#define L3_STAGEB (TILEB + L3_WTILEB)        // 27648
#define SMEM_L3 (NSTAGE * L3_STAGEB)         // 82944

// weight concat offsets (elements)
#define WOFF0 0
#define WOFF1 262144
#define WOFF2 1572864
#define WOFF3 3932160
#define WTOT  4784128

__device__ __half g_act[(size_t)B_ROWS * ACT_W];
__device__ __half g_w[WTOT];
__device__ float  g_logits[(size_t)B_ROWS * 256];

__device__ __forceinline__ uint32_t smem_u32(const void* p) {
    uint32_t a;
    asm("{ .reg .u64 t; cvta.to.shared.u64 t, %1; cvt.u32.u64 %0, t; }" : "=r"(a) : "l"(p));
    return a;
}

#define CP_ASYNC16(dst, src) \
    asm volatile("cp.async.cg.shared.global [%0], [%1], 16;" :: "r"(dst), "l"(src))
#define CP_COMMIT()  asm volatile("cp.async.commit_group;" ::: "memory")
#define CP_WAIT2()   asm volatile("cp.async.wait_group 2;" ::: "memory")
#define CP_WAIT0()   asm volatile("cp.async.wait_group 0;" ::: "memory")

#define LDSM_X4(r0, r1, r2, r3, a) \
    asm volatile("ldmatrix.sync.aligned.m8n8.x4.shared.b16 {%0,%1,%2,%3}, [%4];" \
        : "=r"(r0), "=r"(r1), "=r"(r2), "=r"(r3) : "r"(a))

#define MMA_F16(d, a, b) \
    asm volatile("mma.sync.aligned.m16n8k16.row.col.f32.f16.f16.f32 " \
        "{%0,%1,%2,%3}, {%4,%5,%6,%7}, {%8,%9}, {%0,%1,%2,%3};" \
        : "+f"((d)[0]), "+f"((d)[1]), "+f"((d)[2]), "+f"((d)[3]) \
        : "r"((a)[0]), "r"((a)[1]), "r"((a)[2]), "r"((a)[3]), \
          "r"((b)[0]), "r"((b)[1]))

// ---------------------------------------------------------------------------
// Layers 0-2 GEMM (unchanged from R15 winner): CTA 128x128, warp tile 64x32.
// bias + BN + ReLU -> fp16 out (row stride ACT_W).
// ---------------------------------------------------------------------------
__global__ __launch_bounds__(256, 2)
void mma_gemm_bn(const __half* __restrict__ A,
                 const __half* __restrict__ Wh,
                 const float* __restrict__ bias,
                 const float* __restrict__ gg, const float* __restrict__ be,
                 const float* __restrict__ rm, const float* __restrict__ rv,
                 __half* __restrict__ Ch, int K)
{
    extern __shared__ char smem[];
    const uint32_t sbuf = smem_u32(smem);

    const int tid    = threadIdx.x;
    const int lane   = tid & 31;
    const int wid    = tid >> 5;
    const int warp_m = wid & 1;        // 2 warps over M (64 rows each)
    const int warp_n = wid >> 1;       // 4 warps over N (32 cols each)
    const int row0   = blockIdx.y * TBM;
    const int col0   = blockIdx.x * TBN;

    const int n_iter = K / KC;

    float acc[4][4][4];
    #pragma unroll
    for (int i = 0; i < 4; i++)
        #pragma unroll
        for (int j = 0; j < 4; j++)
            #pragma unroll
            for (int l = 0; l < 4; l++)
                acc[i][j][l] = 0.f;

    auto load_stage = [&](int s) {
        const int k0  = s * KC;
        const uint32_t sb = sbuf + (s % NSTAGE) * STAGEB;
        #pragma unroll
        for (int i = 0; i < 8; i++) {
            const int idx = tid + (i << 8);       // 0..2047
            const int t   = idx >> 10;            // tile 0..1
            const int w   = idx & 1023;
            const int r   = w >> 3;               // row 0..127
            const int c   = w & 7;                // 16B chunk 0..7
            const uint32_t dst = sb + t * TILEB + r * ROWB + c * 16;
            const __half* src;
            if (t == 0) src = A  + (size_t)(row0 + r) * ACT_W + k0 + c * 8;
            else        src = Wh + (size_t)(col0 + r) * K     + k0 + c * 8;
            CP_ASYNC16(dst, src);
        }
    };

    const uint32_t a_off = (uint32_t)((warp_m * 64 + (lane & 15)) * ROWB + (lane >> 4) * 16);
    const uint32_t b_off = (uint32_t)((warp_n * 32 + (lane >> 4) * 8 + (lane & 7)) * ROWB
                                      + ((lane >> 3) & 1) * 16);

    load_stage(0); CP_COMMIT();
    load_stage(1); CP_COMMIT();

    for (int it = 0; it < n_iter; it++) {
        if (it + 2 < n_iter) load_stage(it + 2);
        CP_COMMIT();
        CP_WAIT2();
        __syncthreads();

        const uint32_t sb = sbuf + (it % NSTAGE) * STAGEB;
        #pragma unroll
        for (int kk = 0; kk < 4; kk++) {         // four k16 steps
            uint32_t ah[4][4], bh[4][2];
            #pragma unroll
            for (int mt = 0; mt < 4; mt++) {
                const uint32_t aa = sb + a_off + mt * (16 * ROWB) + kk * 32;
                LDSM_X4(ah[mt][0], ah[mt][1], ah[mt][2], ah[mt][3], aa);
            }
            #pragma unroll
            for (int bt = 0; bt < 2; bt++) {
                const uint32_t ba = sb + TILEB + b_off + bt * (16 * ROWB) + kk * 32;
                uint32_t r0, r1, r2, r3;
                LDSM_X4(r0, r1, r2, r3, ba);
                bh[bt * 2][0] = r0;     bh[bt * 2][1] = r1;
                bh[bt * 2 + 1][0] = r2; bh[bt * 2 + 1][1] = r3;
            }
            #pragma unroll
            for (int mt = 0; mt < 4; mt++)
                #pragma unroll
                for (int nt = 0; nt < 4; nt++)
                    MMA_F16(acc[mt][nt], ah[mt], bh[nt]);
        }
        __syncthreads();
    }
    CP_WAIT0();

    #pragma unroll
    for (int nt = 0; nt < 4; nt++) {
        const int f = col0 + warp_n * 32 + nt * 8 + (lane & 3) * 2;
        const float bs0 = bias[f], bs1 = bias[f + 1];
        const float sc0 = gg[f]     * rsqrtf(rv[f]     + EPS);
        const float sc1 = gg[f + 1] * rsqrtf(rv[f + 1] + EPS);
        const float sh0 = be[f]     - rm[f]     * sc0;
        const float sh1 = be[f + 1] - rm[f + 1] * sc1;
        #pragma unroll
        for (int mt = 0; mt < 4; mt++) {
            const int r = row0 + warp_m * 64 + mt * 16 + (lane >> 2);
            #pragma unroll
            for (int half = 0; half < 2; half++) {
                const int rr = r + half * 8;
                float v0 = acc[mt][nt][half * 2]     + bs0;
                float v1 = acc[mt][nt][half * 2 + 1] + bs1;
                v0 = fmaxf(fmaf(v0, sc0, sh0), 0.f);
                v1 = fmaxf(fmaf(v1, sc1, sh1), 0.f);
                __half2 hp; hp.x = __float2half(v0); hp.y = __float2half(v1);
                *reinterpret_cast<__half2*>(Ch + (size_t)rr * ACT_W + f) = hp;
            }
        }
    }
}

// ---------------------------------------------------------------------------
// Layer 3 GEMM: CTA 128x64, 256 threads, warp grid 4(M)x2(N), warp tile 32x32.
// Grid (4,64) = 256 CTAs -> 2 CTAs/SM nearly everywhere.
// bias only -> fp32 logits (row stride 256).
// ---------------------------------------------------------------------------
__global__ __launch_bounds__(256, 2)
void mma_gemm_l3(const __half* __restrict__ A,
                 const __half* __restrict__ Wh,
                 const float* __restrict__ bias,
                 float* __restrict__ Cf, int K)
{
    extern __shared__ char smem[];
    const uint32_t sbuf = smem_u32(smem);

    const int tid    = threadIdx.x;
    const int lane   = tid & 31;
    const int wid    = tid >> 5;
    const int warp_m = wid & 3;        // 4 warps over M (32 rows each)
    const int warp_n = wid >> 2;       // 2 warps over N (32 cols each)
    const int row0   = blockIdx.y * TBM;
    const int col0   = blockIdx.x * L3_TBN;

    const int n_iter = K / KC;

    float acc[2][4][4];
    #pragma unroll
    for (int i = 0; i < 2; i++)
        #pragma unroll
        for (int j = 0; j < 4; j++)
            #pragma unroll
            for (int l = 0; l < 4; l++)
                acc[i][j][l] = 0.f;

    // loader: (128 + 64) rows * 8 chunks of 16B = 1536 = 6 x 256
    auto load_stage = [&](int s) {
        const int k0  = s * KC;
        const uint32_t sb = sbuf + (s % NSTAGE) * L3_STAGEB;
        #pragma unroll
        for (int i = 0; i < 6; i++) {
            const int idx = tid + (i << 8);       // 0..1535
            const int c   = idx & 7;
            if (idx < 1024) {
                const int r = idx >> 3;
                CP_ASYNC16(sb + r * ROWB + c * 16,
                           A + (size_t)(row0 + r) * ACT_W + k0 + c * 8);
            } else {
                const int r = (idx - 1024) >> 3;  // 0..63
                CP_ASYNC16(sb + TILEB + r * ROWB + c * 16,
                           Wh + (size_t)(col0 + r) * K + k0 + c * 8);
            }
        }
    };

    const uint32_t a_off = (uint32_t)((warp_m * 32 + (lane & 15)) * ROWB + (lane >> 4) * 16);
    const uint32_t b_off = (uint32_t)((warp_n * 32 + (lane >> 4) * 8 + (lane & 7)) * ROWB
                                      + ((lane >> 3) & 1) * 16);

    load_stage(0); CP_COMMIT();
    load_stage(1); CP_COMMIT();

    for (int it = 0; it < n_iter; it++) {
        if (it + 2 < n_iter) load_stage(it + 2);
        CP_COMMIT();
        CP_WAIT2();
        __syncthreads();

        const uint32_t sb = sbuf + (it % NSTAGE) * L3_STAGEB;
        #pragma unroll
        for (int kk = 0; kk < 4; kk++) {
            uint32_t ah[2][4], bh[4][2];
            #pragma unroll
            for (int mt = 0; mt < 2; mt++) {
                const uint32_t aa = sb + a_off + mt * (16 * ROWB) + kk * 32;
                LDSM_X4(ah[mt][0], ah[mt][1], ah[mt][2], ah[mt][3], aa);
            }
            #pragma unroll
            for (int bt = 0; bt < 2; bt++) {
                const uint32_t ba = sb + TILEB + b_off + bt * (16 * ROWB) + kk * 32;
                uint32_t r0, r1, r2, r3;
                LDSM_X4(r0, r1, r2, r3, ba);
                bh[bt * 2][0] = r0;     bh[bt * 2][1] = r1;
                bh[bt * 2 + 1][0] = r2; bh[bt * 2 + 1][1] = r3;
            }
            #pragma unroll
            for (int mt = 0; mt < 2; mt++)
                #pragma unroll
                for (int nt = 0; nt < 4; nt++)
                    MMA_F16(acc[mt][nt], ah[mt], bh[nt]);
        }
        __syncthreads();
    }
    CP_WAIT0();

    #pragma unroll
    for (int nt = 0; nt < 4; nt++) {
        const int f = col0 + warp_n * 32 + nt * 8 + (lane & 3) * 2;
        const float bs0 = bias[f], bs1 = bias[f + 1];
        #pragma unroll
        for (int mt = 0; mt < 2; mt++) {
            const int r = row0 + warp_m * 32 + mt * 16 + (lane >> 2);
            #pragma unroll
            for (int half = 0; half < 2; half++) {
                const int rr = r + half * 8;
                float2 o;
                o.x = acc[mt][nt][half * 2]     + bs0;
                o.y = acc[mt][nt][half * 2 + 1] + bs1;
                *reinterpret_cast<float2*>(Cf + (size_t)rr * 256 + f) = o;
            }
        }
    }
}

// ---------------------------------------------------------------------------
// conversions
// ---------------------------------------------------------------------------
__global__ void cvt_w_all(const float* __restrict__ W0, const float* __restrict__ W1,
                          const float* __restrict__ W2, const float* __restrict__ W3)
{
    const int i = (blockIdx.x * blockDim.x + threadIdx.x) * 8;   // < WTOT
    const float* src;
    int base;
    if (i < WOFF1)      { src = W0; base = WOFF0; }
    else if (i < WOFF2) { src = W1; base = WOFF1; }
    else if (i < WOFF3) { src = W2; base = WOFF2; }
    else                { src = W3; base = WOFF3; }
    const int j = i - base;
    float4 a = *reinterpret_cast<const float4*>(src + j);
    float4 b = *reinterpret_cast<const float4*>(src + j + 4);
    __half2 h[4];
    h[0] = __floats2half2_rn(a.x, a.y);
    h[1] = __floats2half2_rn(a.z, a.w);
    h[2] = __floats2half2_rn(b.x, b.y);
    h[3] = __floats2half2_rn(b.z, b.w);
    *reinterpret_cast<uint4*>(g_w + i) = *reinterpret_cast<uint4*>(h);
}

__global__ void cvt_x_kernel(const float* __restrict__ x)
{
    int i = (blockIdx.x * blockDim.x + threadIdx.x) * 8;      // over 8192*256
    int r = i >> 8;
    int c = i & 255;
    float4 a = *reinterpret_cast<const float4*>(x + i);
    float4 b = *reinterpret_cast<const float4*>(x + i + 4);
    __half2 h[4];
    h[0] = __floats2half2_rn(a.x, a.y);
    h[1] = __floats2half2_rn(a.z, a.w);
    h[2] = __floats2half2_rn(b.x, b.y);
    h[3] = __floats2half2_rn(b.z, b.w);
    *reinterpret_cast<uint4*>(g_act + (size_t)r * ACT_W + 3072 + c) =
        *reinterpret_cast<uint4*>(h);
}

// ---------------------------------------------------------------------------
// Segmented softmax: one block per row, 320 threads (10 warps).
// Warp s reduces segment s (width <= 89) via shuffles.
// ---------------------------------------------------------------------------
__global__ __launch_bounds__(320)
void seg_softmax_kernel(const int* __restrict__ seg_ids,
                        float* __restrict__ out)
{
    __shared__ float vals[256];
    __shared__ int   sseg[256];
    __shared__ int   segstart[NSEG];
    __shared__ int   segend[NSEG];
    __shared__ float smax[NSEG];
    __shared__ float ssum[NSEG];

    const int row  = blockIdx.x;
    const int t    = threadIdx.x;
    const int lane = t & 31;
    const int w    = t >> 5;           // 0..9

    float v = 0.f;
    int sg = 0;
    if (t < 256) {
        v  = g_logits[(size_t)row * 256 + t];
        sg = seg_ids[t];
        vals[t] = v;
        sseg[t] = sg;
    }
    __syncthreads();

    if (t < 256) {
        if (t == 0 || sseg[t - 1] != sg) segstart[sg] = t;
        if (t == 255 || sseg[t + 1] != sg) segend[sg] = t + 1;
    }
    __syncthreads();

    // warp w handles segment w
    {
        const int s0 = segstart[w];
        const int s1 = segend[w];
        float m = -3.402823466e+38f;
        for (int i = s0 + lane; i < s1; i += 32) m = fmaxf(m, vals[i]);
        #pragma unroll
        for (int o = 16; o > 0; o >>= 1)
            m = fmaxf(m, __shfl_xor_sync(0xFFFFFFFFu, m, o));
        float sum = 0.f;
        for (int i = s0 + lane; i < s1; i += 32) {
            float e = expf(vals[i] - m);
            sum += e;
        }
        #pragma unroll
        for (int o = 16; o > 0; o >>= 1)
            sum += __shfl_xor_sync(0xFFFFFFFFu, sum, o);
        if (lane == 0) { smax[w] = m; ssum[w] = sum; }
    }
    __syncthreads();

    if (t < 256)
        out[(size_t)row * 256 + t] = expf(v - smax[sg]) / ssum[sg];
}

// ---------------------------------------------------------------------------
// Launch
// ---------------------------------------------------------------------------
extern "C" void kernel_launch(void* const* d_in, const int* in_sizes, int n_in,
                              void* d_out, int out_size)
{
    const float* x   = (const float*)d_in[0];
    const float* W0  = (const float*)d_in[1];
    const float* b0  = (const float*)d_in[2];
    const float* g0  = (const float*)d_in[3];
    const float* be0 = (const float*)d_in[4];
    const float* rm0 = (const float*)d_in[5];
    const float* rv0 = (const float*)d_in[6];
    const float* W1  = (const float*)d_in[7];
    const float* b1  = (const float*)d_in[8];
    const float* g1  = (const float*)d_in[9];
    const float* be1 = (const float*)d_in[10];
    const float* rm1 = (const float*)d_in[11];
    const float* rv1 = (const float*)d_in[12];
    const float* W2  = (const float*)d_in[13];
    const float* b2  = (const float*)d_in[14];
    const float* g2  = (const float*)d_in[15];
    const float* be2 = (const float*)d_in[16];
    const float* rm2 = (const float*)d_in[17];
    const float* rv2 = (const float*)d_in[18];
    const float* W3  = (const float*)d_in[19];
    const float* b3  = (const float*)d_in[20];
    const int*   seg = (const int*)d_in[21];

    __half *act = nullptr, *wh = nullptr;
    float* logits = nullptr;
    cudaGetSymbolAddress((void**)&act, g_act);
    cudaGetSymbolAddress((void**)&wh, g_w);
    cudaGetSymbolAddress((void**)&logits, g_logits);

    cudaFuncSetAttribute(mma_gemm_bn, cudaFuncAttributeMaxDynamicSharedMemorySize, SMEM_BYTES);
    cudaFuncSetAttribute(mma_gemm_l3, cudaFuncAttributeMaxDynamicSharedMemorySize, SMEM_L3);

    // prologue: conversions
    cvt_x_kernel<<<(B_ROWS * 256) / (256 * 8), 256>>>(x);
    cvt_w_all<<<WTOT / (256 * 8), 256>>>(W0, W1, W2, W3);

    dim3 blk(256);
    dim3 grid1024(1024 / TBN, B_ROWS / TBM);   // (8, 64)
    dim3 gridL3(256 / L3_TBN, B_ROWS / TBM);   // (4, 64) = 256 CTAs

    mma_gemm_bn<<<grid1024, blk, SMEM_BYTES>>>(act + 3072, wh + WOFF0,
                                               b0, g0, be0, rm0, rv0,
                                               act + 2048, 256);
    mma_gemm_bn<<<grid1024, blk, SMEM_BYTES>>>(act + 2048, wh + WOFF1,
                                               b1, g1, be1, rm1, rv1,
                                               act + 1024, 1280);
    mma_gemm_bn<<<grid1024, blk, SMEM_BYTES>>>(act + 1024, wh + WOFF2,
                                               b2, g2, be2, rm2, rv2,
                                               act, 2304);
    mma_gemm_l3<<<gridL3, blk, SMEM_L3>>>(act, wh + WOFF3, b3, logits, 3328);

    seg_softmax_kernel<<<B_ROWS, 320>>>(seg, (float*)d_out);
}